// round 1
// baseline (speedup 1.0000x reference)
#include <cuda_runtime.h>
#include <cuda_bf16.h>
#include <math.h>

#define N_NODES 50000
#define N_EDGES 1600000
#define IN_FEATS 256
#define HF 128           // N_HEADS * OUT_FEATS
#define NEG_SLOPE 0.2f

// -------- device scratch (static allocation; no cudaMalloc allowed) --------
__device__ float g_ft[(size_t)N_NODES * HF];    // projected features [N,128]
__device__ float g_el[N_NODES * 2];             // left logits per head
__device__ float g_er[N_NODES * 2];             // right logits per head
__device__ int   g_deg[N_NODES];                // in-degree histogram
__device__ int   g_off[N_NODES + 1];            // CSR offsets
__device__ int   g_cursor[N_NODES];             // scatter cursors
__device__ int   g_ssrc[N_EDGES];               // src ids sorted by dst

// ---------------------------------------------------------------------------
// Kernel 1: ft = feat @ W   (M=50000, K=256, N=128) fp32 tiled SGEMM
// ---------------------------------------------------------------------------
__global__ void sgemm128(const float* __restrict__ A, const float* __restrict__ B,
                         float* __restrict__ C, int M) {
    __shared__ float As[16][128];   // [k][m]
    __shared__ float Bs[16][128];   // [k][n]
    const int tid = threadIdx.x;           // 256 threads
    const int m0  = blockIdx.x * 128;
    const int tm  = (tid >> 4) << 3;       // thread tile row base (0..120)
    const int tn  = (tid & 15) << 3;       // thread tile col base

    float acc[8][8];
    #pragma unroll
    for (int i = 0; i < 8; i++)
        #pragma unroll
        for (int j = 0; j < 8; j++) acc[i][j] = 0.f;

    const int ar = tid >> 2;               // 0..63
    const int ac = (tid & 3) << 2;         // 0,4,8,12
    const int br = tid >> 5;               // 0..7
    const int bc = (tid & 31) << 2;        // 0..124

    for (int k0 = 0; k0 < IN_FEATS; k0 += 16) {
        #pragma unroll
        for (int r = 0; r < 2; r++) {
            int row = m0 + ar + r * 64;
            float4 v = make_float4(0.f, 0.f, 0.f, 0.f);
            if (row < M) v = *(const float4*)(A + (size_t)row * IN_FEATS + k0 + ac);
            As[ac + 0][ar + r * 64] = v.x;
            As[ac + 1][ar + r * 64] = v.y;
            As[ac + 2][ar + r * 64] = v.z;
            As[ac + 3][ar + r * 64] = v.w;
        }
        #pragma unroll
        for (int r = 0; r < 2; r++) {
            int row = br + r * 8;
            float4 v = *(const float4*)(B + (size_t)(k0 + row) * HF + bc);
            *(float4*)(&Bs[row][bc]) = v;
        }
        __syncthreads();
        #pragma unroll
        for (int k = 0; k < 16; k++) {
            float a[8], b[8];
            #pragma unroll
            for (int i = 0; i < 8; i++) a[i] = As[k][tm + i];
            #pragma unroll
            for (int j = 0; j < 8; j++) b[j] = Bs[k][tn + j];
            #pragma unroll
            for (int i = 0; i < 8; i++)
                #pragma unroll
                for (int j = 0; j < 8; j++)
                    acc[i][j] = fmaf(a[i], b[j], acc[i][j]);
        }
        __syncthreads();
    }
    #pragma unroll
    for (int i = 0; i < 8; i++) {
        int row = m0 + tm + i;
        if (row < M) {
            #pragma unroll
            for (int j = 0; j < 8; j += 4)
                *(float4*)(C + (size_t)row * HF + tn + j) =
                    make_float4(acc[i][j], acc[i][j+1], acc[i][j+2], acc[i][j+3]);
        }
    }
}

// ---------------------------------------------------------------------------
// Kernel 2: el/er = <ft, attn_l/attn_r> per head. One warp per node.
// lanes 0..15 -> head 0, lanes 16..31 -> head 1 (4 floats each).
// ---------------------------------------------------------------------------
__global__ void attn_proj(const float* __restrict__ ft, const float* __restrict__ al,
                          const float* __restrict__ ar_, float* __restrict__ el,
                          float* __restrict__ er) {
    int gtid = blockIdx.x * blockDim.x + threadIdx.x;
    int node = gtid >> 5;
    int lane = gtid & 31;
    if (node >= N_NODES) return;
    float4 f  = *(const float4*)(ft  + (size_t)node * HF + lane * 4);
    float4 wl = *(const float4*)(al  + lane * 4);
    float4 wr = *(const float4*)(ar_ + lane * 4);
    float pl = f.x * wl.x + f.y * wl.y + f.z * wl.z + f.w * wl.w;
    float pr = f.x * wr.x + f.y * wr.y + f.z * wr.z + f.w * wr.w;
    #pragma unroll
    for (int off = 8; off; off >>= 1) {
        pl += __shfl_xor_sync(0xffffffffu, pl, off);
        pr += __shfl_xor_sync(0xffffffffu, pr, off);
    }
    if ((lane & 15) == 0) {
        int h = lane >> 4;
        el[node * 2 + h] = pl;
        er[node * 2 + h] = pr;
    }
}

// ---------------------------------------------------------------------------
// CSR build: zero -> histogram -> scan -> scatter
// ---------------------------------------------------------------------------
__global__ void zero_deg() {
    int i = blockIdx.x * blockDim.x + threadIdx.x;
    if (i < N_NODES) g_deg[i] = 0;
}

__global__ void hist_dst(const int* __restrict__ dst) {
    int i = blockIdx.x * blockDim.x + threadIdx.x;
    if (i < N_EDGES) atomicAdd(&g_deg[dst[i]], 1);
}

__global__ void scan_deg() {
    __shared__ int sm[1024];
    __shared__ int sbase;
    int tid = threadIdx.x;
    if (tid == 0) { sbase = 0; g_off[0] = 0; }
    __syncthreads();
    for (int base = 0; base < N_NODES; base += 1024) {
        int i = base + tid;
        int v = (i < N_NODES) ? g_deg[i] : 0;
        sm[tid] = v;
        __syncthreads();
        for (int d = 1; d < 1024; d <<= 1) {
            int t = (tid >= d) ? sm[tid - d] : 0;
            __syncthreads();
            sm[tid] += t;
            __syncthreads();
        }
        int inc = sm[tid] + sbase;
        if (i < N_NODES) { g_off[i + 1] = inc; g_cursor[i] = inc - v; }
        __syncthreads();
        if (tid == 1023) sbase = inc;
        __syncthreads();
    }
}

__global__ void scatter_edges(const int* __restrict__ src, const int* __restrict__ dst) {
    int i = blockIdx.x * blockDim.x + threadIdx.x;
    if (i < N_EDGES) {
        int p = atomicAdd(&g_cursor[dst[i]], 1);
        g_ssrc[p] = src[i];
    }
}

// ---------------------------------------------------------------------------
// Kernel 3: per-dst softmax + weighted aggregation.
// One 128-thread block per dst node. Unnormalized accumulate, divide at end.
// ---------------------------------------------------------------------------
__global__ void gat_agg(float* __restrict__ out) {
    const int node = blockIdx.x;
    const int tid  = threadIdx.x;            // 128
    const int beg  = g_off[node];
    const int end  = g_off[node + 1];
    const float er0 = g_er[node * 2 + 0];
    const float er1 = g_er[node * 2 + 1];
    const int head1 = tid >> 6;              // 0 or 1

    __shared__ float red0[128], red1[128];
    __shared__ float p0s[128], p1s[128];
    __shared__ int   srcs[128];

    // -------- phase 1: per-head max over incoming edges --------
    float m0 = -3.402823e38f, m1 = -3.402823e38f;
    for (int i = beg + tid; i < end; i += 128) {
        int sv = g_ssrc[i];
        float e0 = g_el[sv * 2 + 0] + er0; e0 = e0 > 0.f ? e0 : NEG_SLOPE * e0;
        float e1 = g_el[sv * 2 + 1] + er1; e1 = e1 > 0.f ? e1 : NEG_SLOPE * e1;
        m0 = fmaxf(m0, e0); m1 = fmaxf(m1, e1);
    }
    red0[tid] = m0; red1[tid] = m1;
    __syncthreads();
    for (int w = 64; w > 0; w >>= 1) {
        if (tid < w) {
            red0[tid] = fmaxf(red0[tid], red0[tid + w]);
            red1[tid] = fmaxf(red1[tid], red1[tid + w]);
        }
        __syncthreads();
    }
    m0 = red0[0]; m1 = red1[0];
    __syncthreads();

    // -------- phase 2: chunked exp + unnormalized accumulate --------
    float acc = 0.f;
    float s0 = 0.f, s1 = 0.f;
    for (int cbeg = beg; cbeg < end; cbeg += 128) {
        int cnt = min(128, end - cbeg);
        if (tid < cnt) {
            int sv = g_ssrc[cbeg + tid];
            float e0 = g_el[sv * 2 + 0] + er0; e0 = e0 > 0.f ? e0 : NEG_SLOPE * e0;
            float e1 = g_el[sv * 2 + 1] + er1; e1 = e1 > 0.f ? e1 : NEG_SLOPE * e1;
            float p0 = __expf(e0 - m0), p1 = __expf(e1 - m1);
            p0s[tid] = p0; p1s[tid] = p1; srcs[tid] = sv;
            s0 += p0; s1 += p1;
        }
        __syncthreads();
        int e = 0;
        #pragma unroll 4
        for (; e < cnt; e++) {
            float p = head1 ? p1s[e] : p0s[e];
            acc = fmaf(p, g_ft[(size_t)srcs[e] * HF + tid], acc);
        }
        __syncthreads();
    }

    // -------- reduce denominators, write --------
    red0[tid] = s0; red1[tid] = s1;
    __syncthreads();
    for (int w = 64; w > 0; w >>= 1) {
        if (tid < w) {
            red0[tid] += red0[tid + w];
            red1[tid] += red1[tid + w];
        }
        __syncthreads();
    }
    float sden = head1 ? red1[0] : red0[0];
    sden = fmaxf(sden, 1e-20f);
    out[(size_t)node * HF + tid] = acc / sden;
}

// ---------------------------------------------------------------------------
extern "C" void kernel_launch(void* const* d_in, const int* in_sizes, int n_in,
                              void* d_out, int out_size) {
    const float* feat   = (const float*)d_in[0];
    const int*   src    = (const int*)  d_in[1];
    const int*   dst    = (const int*)  d_in[2];
    const float* W      = (const float*)d_in[3];
    const float* attn_l = (const float*)d_in[4];
    const float* attn_r = (const float*)d_in[5];
    float* out = (float*)d_out;

    float* ft_p; cudaGetSymbolAddress((void**)&ft_p, g_ft);
    float* el_p; cudaGetSymbolAddress((void**)&el_p, g_el);
    float* er_p; cudaGetSymbolAddress((void**)&er_p, g_er);

    // 1. projection GEMM
    sgemm128<<<(N_NODES + 127) / 128, 256>>>(feat, W, ft_p, N_NODES);
    // 2. attention logits per node
    attn_proj<<<(N_NODES * 32 + 255) / 256, 256>>>(ft_p, attn_l, attn_r, el_p, er_p);
    // 3. CSR build (counting sort by dst)
    zero_deg<<<(N_NODES + 255) / 256, 256>>>();
    hist_dst<<<(N_EDGES + 255) / 256, 256>>>(dst);
    scan_deg<<<1, 1024>>>();
    scatter_edges<<<(N_EDGES + 255) / 256, 256>>>(src, dst);
    // 4. softmax + aggregation
    gat_agg<<<N_NODES, 128>>>(out);
}

// round 2
// speedup vs baseline: 1.7420x; 1.7420x over previous
#include <cuda_runtime.h>
#include <cuda_bf16.h>
#include <math.h>

#define N_NODES 50000
#define N_EDGES 1600000
#define IN_FEATS 256
#define HF 128           // N_HEADS * OUT_FEATS
#define NEG_SLOPE 0.2f
#define SCAN_BLOCKS 49   // ceil(50000/1024)

// -------- device scratch (static allocation; no cudaMalloc allowed) --------
__device__ float g_ft[(size_t)N_NODES * HF];    // projected features [N,128]
__device__ float g_el[N_NODES * 2];             // left logits per head
__device__ float g_er[N_NODES * 2];             // right logits per head
__device__ int   g_deg[N_NODES];                // in-degree histogram
__device__ int   g_off[N_NODES + 1];            // CSR offsets
__device__ int   g_cursor[N_NODES];             // scatter cursors
__device__ int   g_ssrc[N_EDGES];               // src ids sorted by dst
__device__ int   g_bsum[64];                    // per-scan-block sums
__device__ int   g_boff[64];                    // exclusive scan of block sums

// ---------------------------------------------------------------------------
// Kernel 1: ft = feat @ W   (M=50000, K=256, N=128) fp32 tiled SGEMM
// ---------------------------------------------------------------------------
__global__ void sgemm128(const float* __restrict__ A, const float* __restrict__ B,
                         float* __restrict__ C, int M) {
    __shared__ float As[16][128];   // [k][m]
    __shared__ float Bs[16][128];   // [k][n]
    const int tid = threadIdx.x;           // 256 threads
    const int m0  = blockIdx.x * 128;
    const int tm  = (tid >> 4) << 3;       // thread tile row base (0..120)
    const int tn  = (tid & 15) << 3;       // thread tile col base

    float acc[8][8];
    #pragma unroll
    for (int i = 0; i < 8; i++)
        #pragma unroll
        for (int j = 0; j < 8; j++) acc[i][j] = 0.f;

    const int ar = tid >> 2;               // 0..63
    const int ac = (tid & 3) << 2;         // 0,4,8,12
    const int br = tid >> 5;               // 0..7
    const int bc = (tid & 31) << 2;        // 0..124

    for (int k0 = 0; k0 < IN_FEATS; k0 += 16) {
        #pragma unroll
        for (int r = 0; r < 2; r++) {
            int row = m0 + ar + r * 64;
            float4 v = make_float4(0.f, 0.f, 0.f, 0.f);
            if (row < M) v = *(const float4*)(A + (size_t)row * IN_FEATS + k0 + ac);
            As[ac + 0][ar + r * 64] = v.x;
            As[ac + 1][ar + r * 64] = v.y;
            As[ac + 2][ar + r * 64] = v.z;
            As[ac + 3][ar + r * 64] = v.w;
        }
        #pragma unroll
        for (int r = 0; r < 2; r++) {
            int row = br + r * 8;
            float4 v = *(const float4*)(B + (size_t)(k0 + row) * HF + bc);
            *(float4*)(&Bs[row][bc]) = v;
        }
        __syncthreads();
        #pragma unroll
        for (int k = 0; k < 16; k++) {
            float a[8], b[8];
            #pragma unroll
            for (int i = 0; i < 8; i++) a[i] = As[k][tm + i];
            #pragma unroll
            for (int j = 0; j < 8; j++) b[j] = Bs[k][tn + j];
            #pragma unroll
            for (int i = 0; i < 8; i++)
                #pragma unroll
                for (int j = 0; j < 8; j++)
                    acc[i][j] = fmaf(a[i], b[j], acc[i][j]);
        }
        __syncthreads();
    }
    #pragma unroll
    for (int i = 0; i < 8; i++) {
        int row = m0 + tm + i;
        if (row < M) {
            #pragma unroll
            for (int j = 0; j < 8; j += 4)
                *(float4*)(C + (size_t)row * HF + tn + j) =
                    make_float4(acc[i][j], acc[i][j+1], acc[i][j+2], acc[i][j+3]);
        }
    }
}

// ---------------------------------------------------------------------------
// Kernel 2: el/er = <ft, attn_l/attn_r> per head. One warp per node.
// ---------------------------------------------------------------------------
__global__ void attn_proj(const float* __restrict__ ft, const float* __restrict__ al,
                          const float* __restrict__ ar_, float* __restrict__ el,
                          float* __restrict__ er) {
    int gtid = blockIdx.x * blockDim.x + threadIdx.x;
    int node = gtid >> 5;
    int lane = gtid & 31;
    if (node >= N_NODES) return;
    float4 f  = *(const float4*)(ft  + (size_t)node * HF + lane * 4);
    float4 wl = *(const float4*)(al  + lane * 4);
    float4 wr = *(const float4*)(ar_ + lane * 4);
    float pl = f.x * wl.x + f.y * wl.y + f.z * wl.z + f.w * wl.w;
    float pr = f.x * wr.x + f.y * wr.y + f.z * wr.z + f.w * wr.w;
    #pragma unroll
    for (int off = 8; off; off >>= 1) {
        pl += __shfl_xor_sync(0xffffffffu, pl, off);
        pr += __shfl_xor_sync(0xffffffffu, pr, off);
    }
    if ((lane & 15) == 0) {
        int h = lane >> 4;
        el[node * 2 + h] = pl;
        er[node * 2 + h] = pr;
    }
}

// ---------------------------------------------------------------------------
// CSR build: zero -> histogram -> 3-stage scan -> scatter
// ---------------------------------------------------------------------------
__global__ void zero_deg() {
    int i = blockIdx.x * blockDim.x + threadIdx.x;
    if (i < N_NODES) g_deg[i] = 0;
}

__global__ void hist_dst(const int* __restrict__ dst) {
    int i = blockIdx.x * blockDim.x + threadIdx.x;
    if (i < N_EDGES) atomicAdd(&g_deg[dst[i]], 1);
}

__device__ __forceinline__ int warp_incl_scan(int v, int lane) {
    #pragma unroll
    for (int d = 1; d < 32; d <<= 1) {
        int t = __shfl_up_sync(0xffffffffu, v, d);
        if (lane >= d) v += t;
    }
    return v;
}

// Stage A: per-block (1024-elem) sums
__global__ void scan_a() {
    int tid = threadIdx.x;
    int lane = tid & 31, wid = tid >> 5;
    int i = blockIdx.x * 1024 + tid;
    int v = (i < N_NODES) ? g_deg[i] : 0;
    #pragma unroll
    for (int d = 16; d; d >>= 1) v += __shfl_xor_sync(0xffffffffu, v, d);
    __shared__ int ws[32];
    if (lane == 0) ws[wid] = v;
    __syncthreads();
    if (wid == 0) {
        int t = ws[lane];
        #pragma unroll
        for (int d = 16; d; d >>= 1) t += __shfl_xor_sync(0xffffffffu, t, d);
        if (lane == 0) g_bsum[blockIdx.x] = t;
    }
}

// Stage B: exclusive scan of up to 64 block sums (1 warp)
__global__ void scan_b() {
    int lane = threadIdx.x;  // 32 threads
    int a = (lane < SCAN_BLOCKS) ? g_bsum[lane] : 0;
    int b = (lane + 32 < SCAN_BLOCKS) ? g_bsum[lane + 32] : 0;
    int ai = warp_incl_scan(a, lane);
    int tot = __shfl_sync(0xffffffffu, ai, 31);
    int bi = warp_incl_scan(b, lane) + tot;
    g_boff[lane] = ai - a;
    g_boff[lane + 32] = bi - b;
}

// Stage C: full scan, write offsets + cursors
__global__ void scan_c() {
    int tid = threadIdx.x;
    int lane = tid & 31, wid = tid >> 5;
    int i = blockIdx.x * 1024 + tid;
    int v = (i < N_NODES) ? g_deg[i] : 0;
    int incl = warp_incl_scan(v, lane);
    __shared__ int ws[32];
    if (lane == 31) ws[wid] = incl;
    __syncthreads();
    if (wid == 0) {
        int t = ws[lane];
        t = warp_incl_scan(t, lane);
        ws[lane] = t;
    }
    __syncthreads();
    int base = (wid > 0 ? ws[wid - 1] : 0) + g_boff[blockIdx.x];
    int ginc = incl + base;
    if (i < N_NODES) {
        g_off[i + 1] = ginc;
        g_cursor[i] = ginc - v;
    }
    if (blockIdx.x == 0 && tid == 0) g_off[0] = 0;
}

__global__ void scatter_edges(const int* __restrict__ src, const int* __restrict__ dst) {
    int i = blockIdx.x * blockDim.x + threadIdx.x;
    if (i < N_EDGES) {
        int p = atomicAdd(&g_cursor[dst[i]], 1);
        g_ssrc[p] = src[i];
    }
}

// ---------------------------------------------------------------------------
// Kernel 3: warp-per-node softmax + weighted aggregation, float4 gathers.
// Lanes 0..15 -> head 0 features [0,64), lanes 16..31 -> head 1 features [64,128).
// ---------------------------------------------------------------------------
__global__ void gat_agg(float* __restrict__ out) {
    int gtid = blockIdx.x * blockDim.x + threadIdx.x;
    int node = gtid >> 5;
    int lane = gtid & 31;
    if (node >= N_NODES) return;

    const int beg = g_off[node];
    const int end = g_off[node + 1];
    const float er0 = g_er[node * 2 + 0];
    const float er1 = g_er[node * 2 + 1];
    const int head1 = lane >> 4;

    // -------- pass 1: per-head max (lane e = one edge) --------
    float m0 = -3.402823e38f, m1 = -3.402823e38f;
    for (int i = beg + lane; i < end; i += 32) {
        int sv = g_ssrc[i];
        float2 el = *(const float2*)(g_el + 2 * sv);
        float e0 = el.x + er0; e0 = fmaxf(e0, NEG_SLOPE * e0);
        float e1 = el.y + er1; e1 = fmaxf(e1, NEG_SLOPE * e1);
        m0 = fmaxf(m0, e0); m1 = fmaxf(m1, e1);
    }
    #pragma unroll
    for (int d = 16; d; d >>= 1) {
        m0 = fmaxf(m0, __shfl_xor_sync(0xffffffffu, m0, d));
        m1 = fmaxf(m1, __shfl_xor_sync(0xffffffffu, m1, d));
    }

    // -------- pass 2: exp + unnormalized float4 accumulate --------
    const float4* ftp = (const float4*)g_ft;
    float4 acc = make_float4(0.f, 0.f, 0.f, 0.f);
    float s0 = 0.f, s1 = 0.f;
    for (int cb = beg; cb < end; cb += 32) {
        int i = cb + lane;
        float p0 = 0.f, p1 = 0.f;
        int sv = 0;
        if (i < end) {
            sv = g_ssrc[i];
            float2 el = *(const float2*)(g_el + 2 * sv);
            float e0 = el.x + er0; e0 = fmaxf(e0, NEG_SLOPE * e0);
            float e1 = el.y + er1; e1 = fmaxf(e1, NEG_SLOPE * e1);
            p0 = __expf(e0 - m0);
            p1 = __expf(e1 - m1);
        }
        s0 += p0; s1 += p1;
        int cnt = min(32, end - cb);
        #pragma unroll 4
        for (int e = 0; e < cnt; e++) {
            float pp0 = __shfl_sync(0xffffffffu, p0, e);
            float pp1 = __shfl_sync(0xffffffffu, p1, e);
            int   ss  = __shfl_sync(0xffffffffu, sv, e);
            float pp = head1 ? pp1 : pp0;
            float4 f = ftp[(size_t)ss * 32 + lane];
            acc.x = fmaf(pp, f.x, acc.x);
            acc.y = fmaf(pp, f.y, acc.y);
            acc.z = fmaf(pp, f.z, acc.z);
            acc.w = fmaf(pp, f.w, acc.w);
        }
    }

    // -------- denominators + write --------
    #pragma unroll
    for (int d = 16; d; d >>= 1) {
        s0 += __shfl_xor_sync(0xffffffffu, s0, d);
        s1 += __shfl_xor_sync(0xffffffffu, s1, d);
    }
    float sden = fmaxf(head1 ? s1 : s0, 1e-20f);
    float inv = 1.f / sden;
    float4 o = make_float4(acc.x * inv, acc.y * inv, acc.z * inv, acc.w * inv);
    ((float4*)out)[(size_t)node * 32 + lane] = o;
}

// ---------------------------------------------------------------------------
extern "C" void kernel_launch(void* const* d_in, const int* in_sizes, int n_in,
                              void* d_out, int out_size) {
    const float* feat   = (const float*)d_in[0];
    const int*   src    = (const int*)  d_in[1];
    const int*   dst    = (const int*)  d_in[2];
    const float* W      = (const float*)d_in[3];
    const float* attn_l = (const float*)d_in[4];
    const float* attn_r = (const float*)d_in[5];
    float* out = (float*)d_out;

    float* ft_p; cudaGetSymbolAddress((void**)&ft_p, g_ft);
    float* el_p; cudaGetSymbolAddress((void**)&el_p, g_el);
    float* er_p; cudaGetSymbolAddress((void**)&er_p, g_er);

    // 1. projection GEMM
    sgemm128<<<(N_NODES + 127) / 128, 256>>>(feat, W, ft_p, N_NODES);
    // 2. attention logits per node
    attn_proj<<<(N_NODES * 32 + 255) / 256, 256>>>(ft_p, attn_l, attn_r, el_p, er_p);
    // 3. CSR build (counting sort by dst)
    zero_deg<<<(N_NODES + 255) / 256, 256>>>();
    hist_dst<<<(N_EDGES + 255) / 256, 256>>>(dst);
    scan_a<<<SCAN_BLOCKS, 1024>>>();
    scan_b<<<1, 32>>>();
    scan_c<<<SCAN_BLOCKS, 1024>>>();
    scatter_edges<<<(N_EDGES + 255) / 256, 256>>>(src, dst);
    // 4. softmax + aggregation (warp per node)
    gat_agg<<<(N_NODES * 32 + 255) / 256, 256>>>(out);
}

// round 4
// speedup vs baseline: 2.4154x; 1.3865x over previous
#include <cuda_runtime.h>
#include <cuda_bf16.h>
#include <cuda_fp16.h>
#include <math.h>
#include <stdint.h>

#define N_NODES 50000
#define N_EDGES 1600000
#define IN_FEATS 256
#define HF 128           // N_HEADS * OUT_FEATS
#define NEG_SLOPE 0.2f
#define SCAN_BLOCKS 49   // ceil(50000/1024)

// -------- device scratch --------
__device__ __half g_fth[(size_t)N_NODES * HF];  // projected features fp16
__device__ float g_el[N_NODES * 2];
__device__ float g_er[N_NODES * 2];
__device__ int   g_deg[N_NODES];
__device__ int   g_off[N_NODES + 1];
__device__ int   g_cursor[N_NODES];
__device__ int   g_ssrc[N_EDGES];
__device__ int   g_bsum[64];
__device__ int   g_boff[64];

// ===========================================================================
// helpers
// ===========================================================================
__device__ __forceinline__ uint32_t smem_u32(const void* p) {
    uint32_t a;
    asm("{ .reg .u64 t; cvta.to.shared.u64 t, %1; cvt.u32.u64 %0, t; }" : "=r"(a) : "l"(p));
    return a;
}
__device__ __forceinline__ void ldsm4(uint32_t* r, uint32_t addr) {
    asm volatile("ldmatrix.sync.aligned.m8n8.x4.shared.b16 {%0,%1,%2,%3}, [%4];"
                 : "=r"(r[0]), "=r"(r[1]), "=r"(r[2]), "=r"(r[3]) : "r"(addr));
}
__device__ __forceinline__ void mma16816(float* d, const uint32_t* a, const uint32_t* b) {
    asm volatile("mma.sync.aligned.m16n8k16.row.col.f32.bf16.bf16.f32 "
                 "{%0,%1,%2,%3}, {%4,%5,%6,%7}, {%8,%9}, {%0,%1,%2,%3};"
                 : "+f"(d[0]), "+f"(d[1]), "+f"(d[2]), "+f"(d[3])
                 : "r"(a[0]), "r"(a[1]), "r"(a[2]), "r"(a[3]), "r"(b[0]), "r"(b[1]));
}

// smem byte offsets (dynamic, 64 KB)
#define AHI 0
#define ALO 16384
#define BHI 32768
#define BLO 49152
#define SM_TOTAL 65536

// ===========================================================================
// Kernel 1: bf16-split mma.sync GEMM + fused attn logits + fp16 ft store
// C[50000,128] = A[50000,256] @ W[256,128]
// ===========================================================================
__global__ void __launch_bounds__(256)
gemm_mma(const float* __restrict__ A, const float* __restrict__ W,
         const float* __restrict__ al, const float* __restrict__ ar_,
         __half* __restrict__ fth, float* __restrict__ el, float* __restrict__ er,
         int M) {
    extern __shared__ char smem[];
    const uint32_t sb = smem_u32(smem);
    const int tid = threadIdx.x;
    const int wid = tid >> 5;
    const int lane = tid & 31;
    const int warpRow = wid & 3;    // 4 row-warps of 32 M
    const int warpCol = wid >> 2;   // 2 col-warps of 64 N (= one head each)
    const int m0 = blockIdx.x * 128;

    float acc[2][8][4];
    #pragma unroll
    for (int a = 0; a < 2; a++)
        #pragma unroll
        for (int b = 0; b < 8; b++)
            #pragma unroll
            for (int c = 0; c < 4; c++) acc[a][b][c] = 0.f;

    for (int c = 0; c < 4; c++) {
        const int kc = c * 64;
        // ---- A chunk [128 rows][64 k], split hi/lo, swizzled ----
        #pragma unroll
        for (int i = 0; i < 16; i++) {
            int idx = tid + i * 256;
            int row = idx >> 5, kp = idx & 31;
            int gr = m0 + row;
            float2 a = (gr < M) ? *(const float2*)(A + (size_t)gr * IN_FEATS + kc + kp * 2)
                                : make_float2(0.f, 0.f);
            __nv_bfloat16 hx = __float2bfloat16(a.x), hy = __float2bfloat16(a.y);
            float lx = a.x - __bfloat162float(hx), ly = a.y - __bfloat162float(hy);
            uint32_t off = row * 128 + ((kp * 4) ^ ((row & 7) << 4));
            *(__nv_bfloat162*)(smem + AHI + off) = __halves2bfloat162(hx, hy);
            *(__nv_bfloat162*)(smem + ALO + off) =
                __halves2bfloat162(__float2bfloat16(lx), __float2bfloat16(ly));
        }
        // ---- B chunk: Bs[n][k] = W[kc+k][n], split hi/lo, swizzled ----
        #pragma unroll
        for (int i = 0; i < 32; i++) {
            int idx = tid + i * 256;
            int kr = idx >> 7, n = idx & 127;
            float b = W[(size_t)(kc + kr) * HF + n];
            __nv_bfloat16 h = __float2bfloat16(b);
            float l = b - __bfloat162float(h);
            uint32_t off = n * 128 + ((kr * 2) ^ ((n & 7) << 4));
            *(__nv_bfloat16*)(smem + BHI + off) = h;
            *(__nv_bfloat16*)(smem + BLO + off) = __float2bfloat16(l);
        }
        __syncthreads();

        #pragma unroll
        for (int ks = 0; ks < 4; ks++) {
            uint32_t ahi[2][4], alo[2][4], bh[8][2], bl[8][2];
            #pragma unroll
            for (int tm = 0; tm < 2; tm++) {
                int row = warpRow * 32 + tm * 16 + (lane & 15);
                int kb = ks * 32 + ((lane >> 4) << 4);
                uint32_t off = row * 128 + (kb ^ ((row & 7) << 4));
                ldsm4(ahi[tm], sb + AHI + off);
                ldsm4(alo[tm], sb + ALO + off);
            }
            #pragma unroll
            for (int tp = 0; tp < 4; tp++) {
                int n = warpCol * 64 + tp * 16 + ((lane >> 4) << 3) + (lane & 7);
                int kb = ks * 32 + (((lane >> 3) & 1) << 4);
                uint32_t off = n * 128 + (kb ^ ((n & 7) << 4));
                uint32_t r[4];
                ldsm4(r, sb + BHI + off);
                bh[tp * 2][0] = r[0]; bh[tp * 2][1] = r[1];
                bh[tp * 2 + 1][0] = r[2]; bh[tp * 2 + 1][1] = r[3];
                ldsm4(r, sb + BLO + off);
                bl[tp * 2][0] = r[0]; bl[tp * 2][1] = r[1];
                bl[tp * 2 + 1][0] = r[2]; bl[tp * 2 + 1][1] = r[3];
            }
            #pragma unroll
            for (int tm = 0; tm < 2; tm++)
                #pragma unroll
                for (int tn = 0; tn < 8; tn++) {
                    mma16816(acc[tm][tn], ahi[tm], bh[tn]);
                    mma16816(acc[tm][tn], ahi[tm], bl[tn]);
                    mma16816(acc[tm][tn], alo[tm], bh[tn]);
                }
        }
        __syncthreads();
    }

    // ---- epilogue: fp16 store + fused per-head attention dots ----
    const int qr = lane >> 2, qc = lane & 3;
    #pragma unroll
    for (int tm = 0; tm < 2; tm++) {
        #pragma unroll
        for (int h = 0; h < 2; h++) {
            int row = m0 + warpRow * 32 + tm * 16 + 8 * h + qr;
            float dotl = 0.f, dotr = 0.f;
            #pragma unroll
            for (int tn = 0; tn < 8; tn++) {
                float v0 = acc[tm][tn][2 * h + 0];
                float v1 = acc[tm][tn][2 * h + 1];
                int col = warpCol * 64 + tn * 8 + qc * 2;
                dotl = fmaf(v0, __ldg(al + col), fmaf(v1, __ldg(al + col + 1), dotl));
                dotr = fmaf(v0, __ldg(ar_ + col), fmaf(v1, __ldg(ar_ + col + 1), dotr));
                if (row < M)
                    *(__half2*)(fth + (size_t)row * HF + col) = __floats2half2_rn(v0, v1);
            }
            dotl += __shfl_xor_sync(0xffffffffu, dotl, 1);
            dotl += __shfl_xor_sync(0xffffffffu, dotl, 2);
            dotr += __shfl_xor_sync(0xffffffffu, dotr, 1);
            dotr += __shfl_xor_sync(0xffffffffu, dotr, 2);
            if (qc == 0 && row < M) {
                el[row * 2 + warpCol] = dotl;
                er[row * 2 + warpCol] = dotr;
            }
        }
    }
}

// ===========================================================================
// CSR build
// ===========================================================================
__global__ void hist_dst(const int* __restrict__ dst) {
    int i = blockIdx.x * blockDim.x + threadIdx.x;
    if (i < N_EDGES) atomicAdd(&g_deg[dst[i]], 1);
}

__device__ __forceinline__ int warp_incl_scan(int v, int lane) {
    #pragma unroll
    for (int d = 1; d < 32; d <<= 1) {
        int t = __shfl_up_sync(0xffffffffu, v, d);
        if (lane >= d) v += t;
    }
    return v;
}

__global__ void scan_a() {
    int tid = threadIdx.x;
    int lane = tid & 31, wid = tid >> 5;
    int i = blockIdx.x * 1024 + tid;
    int v = (i < N_NODES) ? g_deg[i] : 0;
    #pragma unroll
    for (int d = 16; d; d >>= 1) v += __shfl_xor_sync(0xffffffffu, v, d);
    __shared__ int ws[32];
    if (lane == 0) ws[wid] = v;
    __syncthreads();
    if (wid == 0) {
        int t = ws[lane];
        #pragma unroll
        for (int d = 16; d; d >>= 1) t += __shfl_xor_sync(0xffffffffu, t, d);
        if (lane == 0) g_bsum[blockIdx.x] = t;
    }
}

__global__ void scan_b() {
    int lane = threadIdx.x;
    int a = (lane < SCAN_BLOCKS) ? g_bsum[lane] : 0;
    int b = (lane + 32 < SCAN_BLOCKS) ? g_bsum[lane + 32] : 0;
    int ai = warp_incl_scan(a, lane);
    int tot = __shfl_sync(0xffffffffu, ai, 31);
    int bi = warp_incl_scan(b, lane) + tot;
    g_boff[lane] = ai - a;
    g_boff[lane + 32] = bi - b;
}

__global__ void scan_c() {
    int tid = threadIdx.x;
    int lane = tid & 31, wid = tid >> 5;
    int i = blockIdx.x * 1024 + tid;
    int v = (i < N_NODES) ? g_deg[i] : 0;
    int incl = warp_incl_scan(v, lane);
    __shared__ int ws[32];
    if (lane == 31) ws[wid] = incl;
    __syncthreads();
    if (wid == 0) ws[lane] = warp_incl_scan(ws[lane], lane);
    __syncthreads();
    int base = (wid > 0 ? ws[wid - 1] : 0) + g_boff[blockIdx.x];
    int ginc = incl + base;
    if (i < N_NODES) {
        g_off[i + 1] = ginc;
        g_cursor[i] = ginc - v;
    }
    if (blockIdx.x == 0 && tid == 0) g_off[0] = 0;
}

__global__ void scatter_edges(const int* __restrict__ src, const int* __restrict__ dst) {
    int i = blockIdx.x * blockDim.x + threadIdx.x;
    if (i < N_EDGES) {
        int p = atomicAdd(&g_cursor[dst[i]], 1);
        g_ssrc[p] = src[i];
    }
}

// ===========================================================================
// warp-per-node single-pass softmax + fp16 aggregation
// ===========================================================================
__global__ void gat_agg(float* __restrict__ out) {
    int gtid = blockIdx.x * blockDim.x + threadIdx.x;
    int node = gtid >> 5;
    int lane = gtid & 31;
    if (node >= N_NODES) return;

    const int beg = g_off[node];
    const int end = g_off[node + 1];
    const float er0 = g_er[node * 2 + 0];
    const float er1 = g_er[node * 2 + 1];
    const int head1 = lane >> 4;

    const uint2* ftp = (const uint2*)g_fth;
    float4 acc = make_float4(0.f, 0.f, 0.f, 0.f);
    float s0 = 0.f, s1 = 0.f;

    for (int cb = beg; cb < end; cb += 32) {
        int i = cb + lane;
        float p0 = 0.f, p1 = 0.f;
        int sv = 0;
        if (i < end) {
            sv = g_ssrc[i];
            float2 elv = *(const float2*)(g_el + 2 * sv);
            float e0 = elv.x + er0; e0 = fmaxf(e0, NEG_SLOPE * e0);
            float e1 = elv.y + er1; e1 = fmaxf(e1, NEG_SLOPE * e1);
            p0 = __expf(e0);
            p1 = __expf(e1);
        }
        s0 += p0; s1 += p1;
        int cnt = min(32, end - cb);
        #pragma unroll 4
        for (int e = 0; e < cnt; e++) {
            float pp0 = __shfl_sync(0xffffffffu, p0, e);
            float pp1 = __shfl_sync(0xffffffffu, p1, e);
            int   ss  = __shfl_sync(0xffffffffu, sv, e);
            float pp = head1 ? pp1 : pp0;
            uint2 v = ftp[(size_t)ss * 32 + lane];
            float2 f0 = __half22float2(*(__half2*)&v.x);
            float2 f1 = __half22float2(*(__half2*)&v.y);
            acc.x = fmaf(pp, f0.x, acc.x);
            acc.y = fmaf(pp, f0.y, acc.y);
            acc.z = fmaf(pp, f1.x, acc.z);
            acc.w = fmaf(pp, f1.y, acc.w);
        }
    }

    #pragma unroll
    for (int d = 16; d; d >>= 1) {
        s0 += __shfl_xor_sync(0xffffffffu, s0, d);
        s1 += __shfl_xor_sync(0xffffffffu, s1, d);
    }
    float inv = 1.f / fmaxf(head1 ? s1 : s0, 1e-20f);
    ((float4*)out)[(size_t)node * 32 + lane] =
        make_float4(acc.x * inv, acc.y * inv, acc.z * inv, acc.w * inv);
}

// ===========================================================================
extern "C" void kernel_launch(void* const* d_in, const int* in_sizes, int n_in,
                              void* d_out, int out_size) {
    const float* feat   = (const float*)d_in[0];
    const int*   src    = (const int*)  d_in[1];
    const int*   dst    = (const int*)  d_in[2];
    const float* W      = (const float*)d_in[3];
    const float* attn_l = (const float*)d_in[4];
    const float* attn_r = (const float*)d_in[5];
    float* out = (float*)d_out;

    __half* fth_p; cudaGetSymbolAddress((void**)&fth_p, g_fth);
    float*  el_p;  cudaGetSymbolAddress((void**)&el_p, g_el);
    float*  er_p;  cudaGetSymbolAddress((void**)&er_p, g_er);
    int*    deg_p; cudaGetSymbolAddress((void**)&deg_p, g_deg);

    cudaFuncSetAttribute(gemm_mma, cudaFuncAttributeMaxDynamicSharedMemorySize, SM_TOTAL);

    // CSR build chain interleaved with GEMM
    cudaMemsetAsync(deg_p, 0, N_NODES * sizeof(int));
    hist_dst<<<(N_EDGES + 255) / 256, 256>>>(dst);
    gemm_mma<<<(N_NODES + 127) / 128, 256, SM_TOTAL>>>(feat, W, attn_l, attn_r,
                                                       fth_p, el_p, er_p, N_NODES);
    scan_a<<<SCAN_BLOCKS, 1024>>>();
    scan_b<<<1, 32>>>();
    scan_c<<<SCAN_BLOCKS, 1024>>>();
    scatter_edges<<<(N_EDGES + 255) / 256, 256>>>(src, dst);
    gat_agg<<<(N_NODES * 32 + 255) / 256, 256>>>(out);
}

// round 5
// speedup vs baseline: 2.6320x; 1.0897x over previous
#include <cuda_runtime.h>
#include <cuda_bf16.h>
#include <cuda_fp16.h>
#include <math.h>
#include <stdint.h>

#define N_NODES 50000
#define N_EDGES 1600000
#define IN_FEATS 256
#define HF 128           // N_HEADS * OUT_FEATS
#define NEG_SLOPE 0.2f
#define SCAN_BLOCKS 49   // ceil(50000/1024)

// -------- device scratch --------
__device__ __half g_fth[(size_t)N_NODES * HF];  // projected features fp16
__device__ float g_el[N_NODES * 2];
__device__ float g_er[N_NODES * 2];
__device__ int   g_deg[N_NODES];
__device__ int   g_off[N_NODES + 1];
__device__ int   g_cursor[N_NODES];
__device__ int   g_ssrc[N_EDGES];
__device__ int   g_bsum[64];

// ===========================================================================
// helpers
// ===========================================================================
__device__ __forceinline__ uint32_t smem_u32(const void* p) {
    uint32_t a;
    asm("{ .reg .u64 t; cvta.to.shared.u64 t, %1; cvt.u32.u64 %0, t; }" : "=r"(a) : "l"(p));
    return a;
}
__device__ __forceinline__ void ldsm4(uint32_t* r, uint32_t addr) {
    asm volatile("ldmatrix.sync.aligned.m8n8.x4.shared.b16 {%0,%1,%2,%3}, [%4];"
                 : "=r"(r[0]), "=r"(r[1]), "=r"(r[2]), "=r"(r[3]) : "r"(addr));
}
__device__ __forceinline__ void mma16816(float* d, const uint32_t* a, const uint32_t* b) {
    asm volatile("mma.sync.aligned.m16n8k16.row.col.f32.bf16.bf16.f32 "
                 "{%0,%1,%2,%3}, {%4,%5,%6,%7}, {%8,%9}, {%0,%1,%2,%3};"
                 : "+f"(d[0]), "+f"(d[1]), "+f"(d[2]), "+f"(d[3])
                 : "r"(a[0]), "r"(a[1]), "r"(a[2]), "r"(a[3]), "r"(b[0]), "r"(b[1]));
}

// smem byte offsets (dynamic, 64 KB)
#define AHI 0
#define ALO 16384
#define BHI 32768
#define BLO 49152
#define SM_TOTAL 65536

// ===========================================================================
// Kernel 1: bf16-split mma.sync GEMM + fused attn logits + fp16 ft store
// ===========================================================================
__global__ void __launch_bounds__(256)
gemm_mma(const float* __restrict__ A, const float* __restrict__ W,
         const float* __restrict__ al, const float* __restrict__ ar_,
         __half* __restrict__ fth, float* __restrict__ el, float* __restrict__ er,
         int M) {
    extern __shared__ char smem[];
    const uint32_t sb = smem_u32(smem);
    const int tid = threadIdx.x;
    const int wid = tid >> 5;
    const int lane = tid & 31;
    const int warpRow = wid & 3;    // 4 row-warps of 32 M
    const int warpCol = wid >> 2;   // 2 col-warps of 64 N (= one head each)
    const int m0 = blockIdx.x * 128;

    float acc[2][8][4];
    #pragma unroll
    for (int a = 0; a < 2; a++)
        #pragma unroll
        for (int b = 0; b < 8; b++)
            #pragma unroll
            for (int c = 0; c < 4; c++) acc[a][b][c] = 0.f;

    for (int c = 0; c < 4; c++) {
        const int kc = c * 64;
        #pragma unroll
        for (int i = 0; i < 16; i++) {
            int idx = tid + i * 256;
            int row = idx >> 5, kp = idx & 31;
            int gr = m0 + row;
            float2 a = (gr < M) ? *(const float2*)(A + (size_t)gr * IN_FEATS + kc + kp * 2)
                                : make_float2(0.f, 0.f);
            __nv_bfloat16 hx = __float2bfloat16(a.x), hy = __float2bfloat16(a.y);
            float lx = a.x - __bfloat162float(hx), ly = a.y - __bfloat162float(hy);
            uint32_t off = row * 128 + ((kp * 4) ^ ((row & 7) << 4));
            *(__nv_bfloat162*)(smem + AHI + off) = __halves2bfloat162(hx, hy);
            *(__nv_bfloat162*)(smem + ALO + off) =
                __halves2bfloat162(__float2bfloat16(lx), __float2bfloat16(ly));
        }
        #pragma unroll
        for (int i = 0; i < 32; i++) {
            int idx = tid + i * 256;
            int kr = idx >> 7, n = idx & 127;
            float b = W[(size_t)(kc + kr) * HF + n];
            __nv_bfloat16 h = __float2bfloat16(b);
            float l = b - __bfloat162float(h);
            uint32_t off = n * 128 + ((kr * 2) ^ ((n & 7) << 4));
            *(__nv_bfloat16*)(smem + BHI + off) = h;
            *(__nv_bfloat16*)(smem + BLO + off) = __float2bfloat16(l);
        }
        __syncthreads();

        #pragma unroll
        for (int ks = 0; ks < 4; ks++) {
            uint32_t ahi[2][4], alo[2][4], bh[8][2], bl[8][2];
            #pragma unroll
            for (int tm = 0; tm < 2; tm++) {
                int row = warpRow * 32 + tm * 16 + (lane & 15);
                int kb = ks * 32 + ((lane >> 4) << 4);
                uint32_t off = row * 128 + (kb ^ ((row & 7) << 4));
                ldsm4(ahi[tm], sb + AHI + off);
                ldsm4(alo[tm], sb + ALO + off);
            }
            #pragma unroll
            for (int tp = 0; tp < 4; tp++) {
                int n = warpCol * 64 + tp * 16 + ((lane >> 4) << 3) + (lane & 7);
                int kb = ks * 32 + (((lane >> 3) & 1) << 4);
                uint32_t off = n * 128 + (kb ^ ((n & 7) << 4));
                uint32_t r[4];
                ldsm4(r, sb + BHI + off);
                bh[tp * 2][0] = r[0]; bh[tp * 2][1] = r[1];
                bh[tp * 2 + 1][0] = r[2]; bh[tp * 2 + 1][1] = r[3];
                ldsm4(r, sb + BLO + off);
                bl[tp * 2][0] = r[0]; bl[tp * 2][1] = r[1];
                bl[tp * 2 + 1][0] = r[2]; bl[tp * 2 + 1][1] = r[3];
            }
            #pragma unroll
            for (int tm = 0; tm < 2; tm++)
                #pragma unroll
                for (int tn = 0; tn < 8; tn++) {
                    mma16816(acc[tm][tn], ahi[tm], bh[tn]);
                    mma16816(acc[tm][tn], ahi[tm], bl[tn]);
                    mma16816(acc[tm][tn], alo[tm], bh[tn]);
                }
        }
        __syncthreads();
    }

    // ---- epilogue: fp16 store + fused per-head attention dots ----
    const int qr = lane >> 2, qc = lane & 3;
    #pragma unroll
    for (int tm = 0; tm < 2; tm++) {
        #pragma unroll
        for (int h = 0; h < 2; h++) {
            int row = m0 + warpRow * 32 + tm * 16 + 8 * h + qr;
            float dotl = 0.f, dotr = 0.f;
            #pragma unroll
            for (int tn = 0; tn < 8; tn++) {
                float v0 = acc[tm][tn][2 * h + 0];
                float v1 = acc[tm][tn][2 * h + 1];
                int col = warpCol * 64 + tn * 8 + qc * 2;
                dotl = fmaf(v0, __ldg(al + col), fmaf(v1, __ldg(al + col + 1), dotl));
                dotr = fmaf(v0, __ldg(ar_ + col), fmaf(v1, __ldg(ar_ + col + 1), dotr));
                if (row < M)
                    *(__half2*)(fth + (size_t)row * HF + col) = __floats2half2_rn(v0, v1);
            }
            dotl += __shfl_xor_sync(0xffffffffu, dotl, 1);
            dotl += __shfl_xor_sync(0xffffffffu, dotl, 2);
            dotr += __shfl_xor_sync(0xffffffffu, dotr, 1);
            dotr += __shfl_xor_sync(0xffffffffu, dotr, 2);
            if (qc == 0 && row < M) {
                el[row * 2 + warpCol] = dotl;
                er[row * 2 + warpCol] = dotr;
            }
        }
    }
}

// ===========================================================================
// CSR build
// ===========================================================================
__global__ void hist_dst(const int* __restrict__ dst) {
    int i = blockIdx.x * blockDim.x + threadIdx.x;
    if (i < N_EDGES) atomicAdd(&g_deg[dst[i]], 1);
}

__device__ __forceinline__ int warp_incl_scan(int v, int lane) {
    #pragma unroll
    for (int d = 1; d < 32; d <<= 1) {
        int t = __shfl_up_sync(0xffffffffu, v, d);
        if (lane >= d) v += t;
    }
    return v;
}

__global__ void scan_a() {
    int tid = threadIdx.x;
    int lane = tid & 31, wid = tid >> 5;
    int i = blockIdx.x * 1024 + tid;
    int v = (i < N_NODES) ? g_deg[i] : 0;
    #pragma unroll
    for (int d = 16; d; d >>= 1) v += __shfl_xor_sync(0xffffffffu, v, d);
    __shared__ int ws[32];
    if (lane == 0) ws[wid] = v;
    __syncthreads();
    if (wid == 0) {
        int t = ws[lane];
        #pragma unroll
        for (int d = 16; d; d >>= 1) t += __shfl_xor_sync(0xffffffffu, t, d);
        if (lane == 0) g_bsum[blockIdx.x] = t;
    }
}

// scan_c: each block redundantly scans the 49 block sums (warp 0), then does
// its 1024-elem scan and writes offsets + cursors. (scan_b eliminated)
__global__ void scan_c() {
    __shared__ int ws[32];
    __shared__ int bexcl[64];
    int tid = threadIdx.x;
    int lane = tid & 31, wid = tid >> 5;
    if (wid == 0) {
        int a = (lane < SCAN_BLOCKS) ? g_bsum[lane] : 0;
        int b = (lane + 32 < SCAN_BLOCKS) ? g_bsum[lane + 32] : 0;
        int ai = warp_incl_scan(a, lane);
        int tot = __shfl_sync(0xffffffffu, ai, 31);
        int bi = warp_incl_scan(b, lane) + tot;
        bexcl[lane] = ai - a;
        bexcl[lane + 32] = bi - b;
    }
    int i = blockIdx.x * 1024 + tid;
    int v = (i < N_NODES) ? g_deg[i] : 0;
    int incl = warp_incl_scan(v, lane);
    if (lane == 31) ws[wid] = incl;
    __syncthreads();
    if (wid == 0) ws[lane] = warp_incl_scan(ws[lane], lane);
    __syncthreads();
    int base = (wid > 0 ? ws[wid - 1] : 0) + bexcl[blockIdx.x];
    int ginc = incl + base;
    if (i < N_NODES) {
        g_off[i + 1] = ginc;
        g_cursor[i] = ginc - v;
    }
    if (blockIdx.x == 0 && tid == 0) g_off[0] = 0;
}

__global__ void scatter_edges(const int* __restrict__ src, const int* __restrict__ dst) {
    int i = blockIdx.x * blockDim.x + threadIdx.x;
    if (i < N_EDGES) {
        int p = atomicAdd(&g_cursor[dst[i]], 1);
        g_ssrc[p] = src[i];
    }
}

// ===========================================================================
// warp-per-node single-pass softmax + fp16 aggregation
// ===========================================================================
__global__ void gat_agg(float* __restrict__ out) {
    int gtid = blockIdx.x * blockDim.x + threadIdx.x;
    int node = gtid >> 5;
    int lane = gtid & 31;
    if (node >= N_NODES) return;

    const int beg = g_off[node];
    const int end = g_off[node + 1];
    const float er0 = g_er[node * 2 + 0];
    const float er1 = g_er[node * 2 + 1];
    const int head1 = lane >> 4;

    const uint2* ftp = (const uint2*)g_fth;
    float4 acc = make_float4(0.f, 0.f, 0.f, 0.f);
    float s0 = 0.f, s1 = 0.f;

    for (int cb = beg; cb < end; cb += 32) {
        int i = cb + lane;
        float p0 = 0.f, p1 = 0.f;
        int sv = 0;
        if (i < end) {
            sv = g_ssrc[i];
            float2 elv = *(const float2*)(g_el + 2 * sv);
            float e0 = elv.x + er0; e0 = fmaxf(e0, NEG_SLOPE * e0);
            float e1 = elv.y + er1; e1 = fmaxf(e1, NEG_SLOPE * e1);
            p0 = __expf(e0);
            p1 = __expf(e1);
        }
        s0 += p0; s1 += p1;
        int cnt = min(32, end - cb);
        #pragma unroll 4
        for (int e = 0; e < cnt; e++) {
            float pp0 = __shfl_sync(0xffffffffu, p0, e);
            float pp1 = __shfl_sync(0xffffffffu, p1, e);
            int   ss  = __shfl_sync(0xffffffffu, sv, e);
            float pp = head1 ? pp1 : pp0;
            uint2 v = ftp[(size_t)ss * 32 + lane];
            float2 f0 = __half22float2(*(__half2*)&v.x);
            float2 f1 = __half22float2(*(__half2*)&v.y);
            acc.x = fmaf(pp, f0.x, acc.x);
            acc.y = fmaf(pp, f0.y, acc.y);
            acc.z = fmaf(pp, f1.x, acc.z);
            acc.w = fmaf(pp, f1.y, acc.w);
        }
    }

    #pragma unroll
    for (int d = 16; d; d >>= 1) {
        s0 += __shfl_xor_sync(0xffffffffu, s0, d);
        s1 += __shfl_xor_sync(0xffffffffu, s1, d);
    }
    float inv = 1.f / fmaxf(head1 ? s1 : s0, 1e-20f);
    ((float4*)out)[(size_t)node * 32 + lane] =
        make_float4(acc.x * inv, acc.y * inv, acc.z * inv, acc.w * inv);
}

// ===========================================================================
extern "C" void kernel_launch(void* const* d_in, const int* in_sizes, int n_in,
                              void* d_out, int out_size) {
    const float* feat   = (const float*)d_in[0];
    const int*   src    = (const int*)  d_in[1];
    const int*   dst    = (const int*)  d_in[2];
    const float* W      = (const float*)d_in[3];
    const float* attn_l = (const float*)d_in[4];
    const float* attn_r = (const float*)d_in[5];
    float* out = (float*)d_out;

    __half* fth_p; cudaGetSymbolAddress((void**)&fth_p, g_fth);
    float*  el_p;  cudaGetSymbolAddress((void**)&el_p, g_el);
    float*  er_p;  cudaGetSymbolAddress((void**)&er_p, g_er);
    int*    deg_p; cudaGetSymbolAddress((void**)&deg_p, g_deg);

    cudaFuncSetAttribute(gemm_mma, cudaFuncAttributeMaxDynamicSharedMemorySize, SM_TOTAL);

    // One-time side stream + fork/join events (handles constant across calls,
    // so the captured graph is identical every call).
    static cudaStream_t s1 = [] {
        cudaStream_t s; cudaStreamCreateWithFlags(&s, cudaStreamNonBlocking); return s;
    }();
    static cudaEvent_t e0 = [] {
        cudaEvent_t e; cudaEventCreateWithFlags(&e, cudaEventDisableTiming); return e;
    }();
    static cudaEvent_t e1 = [] {
        cudaEvent_t e; cudaEventCreateWithFlags(&e, cudaEventDisableTiming); return e;
    }();

    // Fork: GEMM (independent of CSR build) runs on s1.
    cudaEventRecord(e0, 0);
    cudaStreamWaitEvent(s1, e0, 0);
    gemm_mma<<<(N_NODES + 127) / 128, 256, SM_TOTAL, s1>>>(feat, W, attn_l, attn_r,
                                                           fth_p, el_p, er_p, N_NODES);
    cudaEventRecord(e1, s1);

    // Main stream: CSR build chain.
    cudaMemsetAsync(deg_p, 0, N_NODES * sizeof(int));
    hist_dst<<<(N_EDGES + 255) / 256, 256>>>(dst);
    scan_a<<<SCAN_BLOCKS, 1024>>>();
    scan_c<<<SCAN_BLOCKS, 1024>>>();
    scatter_edges<<<(N_EDGES + 255) / 256, 256>>>(src, dst);

    // Join, then aggregate.
    cudaStreamWaitEvent(0, e1, 0);
    gat_agg<<<(N_NODES * 32 + 255) / 256, 256>>>(out);
}